// round 7
// baseline (speedup 1.0000x reference)
#include <cuda_runtime.h>
#include <cuda_bf16.h>
#include <stdint.h>

// Grouped GEMM out[e] = x[e] @ w[e]^T, fp32 I/O, via mma.sync bf16 (HMMA)
// with hi/lo fp32 split (3 passes: Ahi*Bhi + Ahi*Blo + Alo*Bhi).
//   x: [E, M, K], w: [E, N, K], out: [E, M, N]; E=16, M=256, K=2048, N=8192.
// CTA: 128x128 tile, 8 warps (2x4), warp tile 64x32, K-chunks of 32 fp32,
// double-buffered SMEM with 80B-padded rows (16B-aligned rows for ldmatrix;
// 80*r mod 128 covers all eight 16B segments -> conflict-free ldmatrix).

static constexpr int E_DIM = 16;
static constexpr int M_DIM = 256;
static constexpr int K_DIM = 2048;
static constexpr int N_DIM = 8192;

static constexpr int BM = 128;
static constexpr int BN = 128;
static constexpr int KC = 32;                 // fp32 k per chunk
static constexpr int NCHUNK = K_DIM / KC;     // 64

static constexpr int ROW_B   = 80;            // 32 bf16 (64 B) + 16 B pad, 16B-aligned
static constexpr int TILE_B  = 128 * ROW_B;   // 10240 B per bf16 tile
static constexpr int STAGE_B = 4 * TILE_B;    // Ahi, Alo, Bhi, Blo = 40960 B
static constexpr int SMEM_B  = 2 * STAGE_B;   // 81920 B

__device__ __forceinline__ uint32_t smem_u32(const void* p) {
    uint32_t a;
    asm("{ .reg .u64 t; cvta.to.shared.u64 t, %1; cvt.u32.u64 %0, t; }"
        : "=r"(a) : "l"(p));
    return a;
}

// Pack (x,y) into bf16x2 hi limb and bf16x2 lo (residual) limb. x -> low half.
__device__ __forceinline__ void split2(float x, float y, uint32_t& hi, uint32_t& lo) {
    __nv_bfloat162 h = __floats2bfloat162_rn(x, y);
    hi = *reinterpret_cast<uint32_t*>(&h);
    float hx = __uint_as_float(hi << 16);
    float hy = __uint_as_float(hi & 0xffff0000u);
    __nv_bfloat162 l = __floats2bfloat162_rn(x - hx, y - hy);
    lo = *reinterpret_cast<uint32_t*>(&l);
}

__device__ __forceinline__ void ldsm4(uint32_t* r, uint32_t addr) {
    asm volatile("ldmatrix.sync.aligned.m8n8.x4.shared.b16 {%0,%1,%2,%3}, [%4];"
                 : "=r"(r[0]), "=r"(r[1]), "=r"(r[2]), "=r"(r[3]) : "r"(addr));
}

__device__ __forceinline__ void mma16816(float* c, const uint32_t* a,
                                         const uint32_t* b) {
    asm volatile(
        "mma.sync.aligned.m16n8k16.row.col.f32.bf16.bf16.f32 "
        "{%0,%1,%2,%3}, {%4,%5,%6,%7}, {%8,%9}, {%0,%1,%2,%3};"
        : "+f"(c[0]), "+f"(c[1]), "+f"(c[2]), "+f"(c[3])
        : "r"(a[0]), "r"(a[1]), "r"(a[2]), "r"(a[3]), "r"(b[0]), "r"(b[1]));
}

__global__ __launch_bounds__(256, 1)
void grouped_gemm_hmma(const float* __restrict__ X,
                       const float* __restrict__ W,
                       float* __restrict__ O) {
    extern __shared__ char sm[];
    const uint32_t sbase = smem_u32(sm);

    const int tid  = threadIdx.x;
    const int wid  = tid >> 5;
    const int lane = tid & 31;
    const int wm   = wid >> 2;   // 0..1 -> 64-row slab
    const int wn   = wid & 3;    // 0..3 -> 32-col slab

    const int e  = blockIdx.z;
    const int m0 = blockIdx.y * BM;
    const int n0 = blockIdx.x * BN;

    // ---- global load mapping: 2 threads per row, 16 floats each ----
    const int grow = tid >> 1;      // 0..127
    const int ghalf = tid & 1;      // 16-float half of the 32-wide chunk
    const float* Ag = X + ((size_t)e * M_DIM + m0 + grow) * K_DIM + ghalf * 16;
    const float* Bg = W + ((size_t)e * N_DIM + n0 + grow) * K_DIM + ghalf * 16;
    const uint32_t wb = grow * ROW_B + ghalf * 32;   // smem byte base for stores

    // ---- ldmatrix address offsets (within a tile) ----
    // A (m16k16 x4): row = wm*64 + mt*16 + (lane&15), col16B = lane>>4
    const uint32_t aoff = (uint32_t)((wm * 64 + (lane & 15)) * ROW_B + ((lane >> 4) << 4));
    // B (two n8k16 tiles per x4): row = wn*32 + np*16 + ((lane>>4)<<3) + (lane&7),
    //                             col16B = (lane>>3)&1
    const uint32_t boff = (uint32_t)((wn * 32 + ((lane >> 4) << 3) + (lane & 7)) * ROW_B
                                     + (((lane >> 3) & 1) << 4));

    float acc[4][4][4];
#pragma unroll
    for (int i = 0; i < 4; i++)
#pragma unroll
        for (int j = 0; j < 4; j++)
#pragma unroll
            for (int v = 0; v < 4; v++) acc[i][j][v] = 0.0f;

    float4 av[4], bv[4];

    // prologue: chunk 0 -> stage 0
#pragma unroll
    for (int j = 0; j < 4; j++) {
        av[j] = *reinterpret_cast<const float4*>(Ag + j * 4);
        bv[j] = *reinterpret_cast<const float4*>(Bg + j * 4);
    }
    {
        char* ah = sm + 0 * TILE_B; char* al = sm + 1 * TILE_B;
        char* bh = sm + 2 * TILE_B; char* bl = sm + 3 * TILE_B;
#pragma unroll
        for (int j = 0; j < 4; j++) {
            uint32_t h0, l0, h1, l1;
            split2(av[j].x, av[j].y, h0, l0);
            split2(av[j].z, av[j].w, h1, l1);
            *reinterpret_cast<uint2*>(ah + wb + j * 8) = make_uint2(h0, h1);
            *reinterpret_cast<uint2*>(al + wb + j * 8) = make_uint2(l0, l1);
            split2(bv[j].x, bv[j].y, h0, l0);
            split2(bv[j].z, bv[j].w, h1, l1);
            *reinterpret_cast<uint2*>(bh + wb + j * 8) = make_uint2(h0, h1);
            *reinterpret_cast<uint2*>(bl + wb + j * 8) = make_uint2(l0, l1);
        }
    }
    __syncthreads();

#pragma unroll 1
    for (int c = 0; c < NCHUNK; c++) {
        // issue next chunk's loads early (latency hides under the MMAs)
        if (c + 1 < NCHUNK) {
            const int kof = (c + 1) * KC;
#pragma unroll
            for (int j = 0; j < 4; j++) {
                av[j] = *reinterpret_cast<const float4*>(Ag + kof + j * 4);
                bv[j] = *reinterpret_cast<const float4*>(Bg + kof + j * 4);
            }
        }

        // ---- compute from stage c&1 ----
        const uint32_t st = sbase + (uint32_t)((c & 1) * STAGE_B);
        const uint32_t Ahi = st, Alo = st + TILE_B, Bhi = st + 2 * TILE_B, Blo = st + 3 * TILE_B;

#pragma unroll
        for (int ks = 0; ks < 2; ks++) {
            const uint32_t ksb = ks * 32;
            uint32_t ah[4][4], al[4][4], bh[8], bl[8];
#pragma unroll
            for (int mt = 0; mt < 4; mt++) {
                ldsm4(ah[mt], Ahi + aoff + mt * (16 * ROW_B) + ksb);
                ldsm4(al[mt], Alo + aoff + mt * (16 * ROW_B) + ksb);
            }
#pragma unroll
            for (int np = 0; np < 2; np++) {
                ldsm4(bh + np * 4, Bhi + boff + np * (16 * ROW_B) + ksb);
                ldsm4(bl + np * 4, Blo + boff + np * (16 * ROW_B) + ksb);
            }
            // pass 1: Ahi * Bhi
#pragma unroll
            for (int mt = 0; mt < 4; mt++)
#pragma unroll
                for (int nt = 0; nt < 4; nt++)
                    mma16816(acc[mt][nt], ah[mt], bh + 2 * nt);
            // pass 2: Ahi * Blo
#pragma unroll
            for (int mt = 0; mt < 4; mt++)
#pragma unroll
                for (int nt = 0; nt < 4; nt++)
                    mma16816(acc[mt][nt], ah[mt], bl + 2 * nt);
            // pass 3: Alo * Bhi
#pragma unroll
            for (int mt = 0; mt < 4; mt++)
#pragma unroll
                for (int nt = 0; nt < 4; nt++)
                    mma16816(acc[mt][nt], al[mt], bh + 2 * nt);
        }

        // ---- store next chunk into stage (c+1)&1 ----
        if (c + 1 < NCHUNK) {
            char* dst = sm + ((c + 1) & 1) * STAGE_B;
            char* ah = dst + 0 * TILE_B; char* al = dst + 1 * TILE_B;
            char* bh = dst + 2 * TILE_B; char* bl = dst + 3 * TILE_B;
#pragma unroll
            for (int j = 0; j < 4; j++) {
                uint32_t h0, l0, h1, l1;
                split2(av[j].x, av[j].y, h0, l0);
                split2(av[j].z, av[j].w, h1, l1);
                *reinterpret_cast<uint2*>(ah + wb + j * 8) = make_uint2(h0, h1);
                *reinterpret_cast<uint2*>(al + wb + j * 8) = make_uint2(l0, l1);
                split2(bv[j].x, bv[j].y, h0, l0);
                split2(bv[j].z, bv[j].w, h1, l1);
                *reinterpret_cast<uint2*>(bh + wb + j * 8) = make_uint2(h0, h1);
                *reinterpret_cast<uint2*>(bl + wb + j * 8) = make_uint2(l0, l1);
            }
        }
        __syncthreads();
    }

    // ---- epilogue: acc frag layout -> fp32 stores (float2, sector-aligned) ----
    float* C = O + (size_t)e * M_DIM * N_DIM;
    const int mrow = m0 + wm * 64 + (lane >> 2);
    const int ncol = n0 + wn * 32 + (lane & 3) * 2;
#pragma unroll
    for (int mt = 0; mt < 4; mt++) {
#pragma unroll
        for (int nt = 0; nt < 4; nt++) {
            float* p0 = C + (size_t)(mrow + mt * 16) * N_DIM + (ncol + nt * 8);
            float* p1 = p0 + 8 * N_DIM;
            *reinterpret_cast<float2*>(p0) = make_float2(acc[mt][nt][0], acc[mt][nt][1]);
            *reinterpret_cast<float2*>(p1) = make_float2(acc[mt][nt][2], acc[mt][nt][3]);
        }
    }
}

extern "C" void kernel_launch(void* const* d_in, const int* in_sizes, int n_in,
                              void* d_out, int out_size) {
    const float* X = (const float*)d_in[0];  // expert_inputs  [E, M, K]
    const float* W = (const float*)d_in[1];  // expert_weights [E, N, K]
    float* O = (float*)d_out;                // [E, M, N]

    cudaFuncSetAttribute(grouped_gemm_hmma,
                         cudaFuncAttributeMaxDynamicSharedMemorySize, SMEM_B);

    dim3 grid(N_DIM / BN, M_DIM / BM, E_DIM);  // (64, 2, 16) = 2048 CTAs
    grouped_gemm_hmma<<<grid, 256, SMEM_B>>>(X, W, O);
}

// round 8
// speedup vs baseline: 1.0739x; 1.0739x over previous
#include <cuda_runtime.h>
#include <cuda_bf16.h>
#include <stdint.h>

// Grouped GEMM out[e] = x[e] @ w[e]^T, fp32 I/O, via mma.sync bf16 (HMMA)
// with hi/lo fp32 split (3 passes: Ahi*Bhi + Ahi*Blo + Alo*Bhi).
//   x: [E, M, K], w: [E, N, K], out: [E, M, N]; E=16, M=256, K=2048, N=8192.
// R8: CTA tile 128x256, 8 warps (2x4), warp tile 64x64 (acc 128 regs) to
// raise the MMA : shared-traffic ratio (ldsm per MMA down 33%, STS/LDG per
// MMA down 25%) — L1 pipe was the co-bottleneck at 79%.
// K-chunks of 32 fp32, double-buffered SMEM, 80B-padded rows (16B-aligned,
// conflict-free ldmatrix).

static constexpr int E_DIM = 16;
static constexpr int M_DIM = 256;
static constexpr int K_DIM = 2048;
static constexpr int N_DIM = 8192;

static constexpr int BM = 128;
static constexpr int BN = 256;
static constexpr int KC = 32;                 // fp32 k per chunk
static constexpr int NCHUNK = K_DIM / KC;     // 64

static constexpr int ROW_B   = 80;            // 64 B payload + 16 B pad
static constexpr int A_TILE  = 128 * ROW_B;   // 10240 B (one limb)
static constexpr int B_TILE  = 256 * ROW_B;   // 20480 B (one limb)
static constexpr int OFF_AHI = 0;
static constexpr int OFF_ALO = A_TILE;
static constexpr int OFF_BHI = 2 * A_TILE;
static constexpr int OFF_BLO = 2 * A_TILE + B_TILE;
static constexpr int STAGE_B = 2 * A_TILE + 2 * B_TILE;  // 61440
static constexpr int SMEM_B  = 2 * STAGE_B;              // 122880

__device__ __forceinline__ uint32_t smem_u32(const void* p) {
    uint32_t a;
    asm("{ .reg .u64 t; cvta.to.shared.u64 t, %1; cvt.u32.u64 %0, t; }"
        : "=r"(a) : "l"(p));
    return a;
}

__device__ __forceinline__ void split2(float x, float y, uint32_t& hi, uint32_t& lo) {
    __nv_bfloat162 h = __floats2bfloat162_rn(x, y);
    hi = *reinterpret_cast<uint32_t*>(&h);
    float hx = __uint_as_float(hi << 16);
    float hy = __uint_as_float(hi & 0xffff0000u);
    __nv_bfloat162 l = __floats2bfloat162_rn(x - hx, y - hy);
    lo = *reinterpret_cast<uint32_t*>(&l);
}

__device__ __forceinline__ void ldsm4(uint32_t* r, uint32_t addr) {
    asm volatile("ldmatrix.sync.aligned.m8n8.x4.shared.b16 {%0,%1,%2,%3}, [%4];"
                 : "=r"(r[0]), "=r"(r[1]), "=r"(r[2]), "=r"(r[3]) : "r"(addr));
}

__device__ __forceinline__ void mma16816(float* c, const uint32_t* a,
                                         const uint32_t* b) {
    asm volatile(
        "mma.sync.aligned.m16n8k16.row.col.f32.bf16.bf16.f32 "
        "{%0,%1,%2,%3}, {%4,%5,%6,%7}, {%8,%9}, {%0,%1,%2,%3};"
        : "+f"(c[0]), "+f"(c[1]), "+f"(c[2]), "+f"(c[3])
        : "r"(a[0]), "r"(a[1]), "r"(a[2]), "r"(a[3]), "r"(b[0]), "r"(b[1]));
}

// Convert one 16-float slot (4 float4) into hi/lo bf16 limbs and STS.
__device__ __forceinline__ void cvt_store(const float4* v, char* hi_t, char* lo_t,
                                          uint32_t wb) {
#pragma unroll
    for (int j = 0; j < 4; j++) {
        uint32_t h0, l0, h1, l1;
        split2(v[j].x, v[j].y, h0, l0);
        split2(v[j].z, v[j].w, h1, l1);
        *reinterpret_cast<uint2*>(hi_t + wb + j * 8) = make_uint2(h0, h1);
        *reinterpret_cast<uint2*>(lo_t + wb + j * 8) = make_uint2(l0, l1);
    }
}

__global__ __launch_bounds__(256, 1)
void grouped_gemm_hmma(const float* __restrict__ X,
                       const float* __restrict__ W,
                       float* __restrict__ O) {
    extern __shared__ char sm[];
    const uint32_t sbase = smem_u32(sm);

    const int tid  = threadIdx.x;
    const int wid  = tid >> 5;
    const int lane = tid & 31;
    const int wm   = wid >> 2;   // 0..1 -> 64-row slab
    const int wn   = wid & 3;    // 0..3 -> 64-col slab

    const int e  = blockIdx.z;
    const int m0 = blockIdx.y * BM;
    const int n0 = blockIdx.x * BN;

    // ---- global load slots: slot i covers (row = tid>>1 [+128 B-rows for i=2],
    //      half = tid&1, 16 floats). Slot 0 = A, slots 1,2 = B. ----
    const int lrow = tid >> 1;
    const int lhalf = tid & 1;
    const float* g0 = X + ((size_t)e * M_DIM + m0 + lrow) * K_DIM + lhalf * 16;
    const float* g1 = W + ((size_t)e * N_DIM + n0 + lrow) * K_DIM + lhalf * 16;
    const float* g2 = W + ((size_t)e * N_DIM + n0 + 128 + lrow) * K_DIM + lhalf * 16;
    const uint32_t wb01 = lrow * ROW_B + lhalf * 32;
    const uint32_t wb2  = (lrow + 128) * ROW_B + lhalf * 32;

    // ---- ldmatrix offsets within a limb tile ----
    const uint32_t aoff = (uint32_t)((wm * 64 + (lane & 15)) * ROW_B + ((lane >> 4) << 4));
    const uint32_t boff = (uint32_t)((wn * 64 + ((lane >> 4) << 3) + (lane & 7)) * ROW_B
                                     + (((lane >> 3) & 1) << 4));

    float acc[4][8][4];
#pragma unroll
    for (int i = 0; i < 4; i++)
#pragma unroll
        for (int j = 0; j < 8; j++)
#pragma unroll
            for (int v = 0; v < 4; v++) acc[i][j][v] = 0.0f;

    float4 fv[12];  // prefetch: 3 slots x 4 float4

    // ---- prologue: chunk 0 -> stage 0 ----
#pragma unroll
    for (int j = 0; j < 4; j++) {
        fv[j]     = *reinterpret_cast<const float4*>(g0 + j * 4);
        fv[4 + j] = *reinterpret_cast<const float4*>(g1 + j * 4);
        fv[8 + j] = *reinterpret_cast<const float4*>(g2 + j * 4);
    }
    cvt_store(fv,     sm + OFF_AHI, sm + OFF_ALO, wb01);
    cvt_store(fv + 4, sm + OFF_BHI, sm + OFF_BLO, wb01);
    cvt_store(fv + 8, sm + OFF_BHI, sm + OFF_BLO, wb2);
    __syncthreads();

#pragma unroll 1
    for (int c = 0; c < NCHUNK; c++) {
        const bool more = (c + 1 < NCHUNK);
        // prefetch next chunk
        if (more) {
            const int kof = (c + 1) * KC;
#pragma unroll
            for (int j = 0; j < 4; j++) {
                fv[j]     = *reinterpret_cast<const float4*>(g0 + kof + j * 4);
                fv[4 + j] = *reinterpret_cast<const float4*>(g1 + kof + j * 4);
                fv[8 + j] = *reinterpret_cast<const float4*>(g2 + kof + j * 4);
            }
        }

        const uint32_t st = sbase + (uint32_t)((c & 1) * STAGE_B);
        const uint32_t Ahi = st + OFF_AHI, Alo = st + OFF_ALO;
        const uint32_t Bhi = st + OFF_BHI, Blo = st + OFF_BLO;

#pragma unroll
        for (int ks = 0; ks < 2; ks++) {
            const uint32_t ksb = ks * 32;
            uint32_t bh[16], bl[16];
#pragma unroll
            for (int np = 0; np < 4; np++) {
                ldsm4(bh + 4 * np, Bhi + boff + np * (16 * ROW_B) + ksb);
                ldsm4(bl + 4 * np, Blo + boff + np * (16 * ROW_B) + ksb);
            }
#pragma unroll
            for (int mt = 0; mt < 4; mt++) {
                uint32_t ah[4], al[4];
                ldsm4(ah, Ahi + aoff + mt * (16 * ROW_B) + ksb);
                ldsm4(al, Alo + aoff + mt * (16 * ROW_B) + ksb);
#pragma unroll
                for (int nt = 0; nt < 8; nt++)
                    mma16816(acc[mt][nt], ah, bh + 2 * nt);
#pragma unroll
                for (int nt = 0; nt < 8; nt++)
                    mma16816(acc[mt][nt], ah, bl + 2 * nt);
#pragma unroll
                for (int nt = 0; nt < 8; nt++)
                    mma16816(acc[mt][nt], al, bh + 2 * nt);
            }

            // between the two ks halves, drain the prefetch into the other stage
            if (ks == 0 && more) {
                char* dst = sm + ((c + 1) & 1) * STAGE_B;
                cvt_store(fv,     dst + OFF_AHI, dst + OFF_ALO, wb01);
                cvt_store(fv + 4, dst + OFF_BHI, dst + OFF_BLO, wb01);
                cvt_store(fv + 8, dst + OFF_BHI, dst + OFF_BLO, wb2);
            }
        }
        __syncthreads();
    }

    // ---- epilogue ----
    float* C = O + (size_t)e * M_DIM * N_DIM;
    const int mrow = m0 + wm * 64 + (lane >> 2);
    const int ncol = n0 + wn * 64 + (lane & 3) * 2;
#pragma unroll
    for (int mt = 0; mt < 4; mt++) {
#pragma unroll
        for (int nt = 0; nt < 8; nt++) {
            float* p0 = C + (size_t)(mrow + mt * 16) * N_DIM + (ncol + nt * 8);
            float* p1 = p0 + 8 * N_DIM;
            *reinterpret_cast<float2*>(p0) = make_float2(acc[mt][nt][0], acc[mt][nt][1]);
            *reinterpret_cast<float2*>(p1) = make_float2(acc[mt][nt][2], acc[mt][nt][3]);
        }
    }
}

extern "C" void kernel_launch(void* const* d_in, const int* in_sizes, int n_in,
                              void* d_out, int out_size) {
    const float* X = (const float*)d_in[0];  // expert_inputs  [E, M, K]
    const float* W = (const float*)d_in[1];  // expert_weights [E, N, K]
    float* O = (float*)d_out;                // [E, M, N]

    cudaFuncSetAttribute(grouped_gemm_hmma,
                         cudaFuncAttributeMaxDynamicSharedMemorySize, SMEM_B);

    dim3 grid(N_DIM / BN, M_DIM / BM, E_DIM);  // (32, 2, 16) = 1024 CTAs
    grouped_gemm_hmma<<<grid, 256, SMEM_B>>>(X, W, O);
}

// round 9
// speedup vs baseline: 1.1819x; 1.1005x over previous
#include <cuda_runtime.h>
#include <cuda_bf16.h>
#include <stdint.h>

// Grouped GEMM out[e] = x[e] @ w[e]^T, fp32 I/O, via mma.sync bf16 (HMMA)
// with hi/lo fp32 split (3 passes: Ahi*Bhi + Ahi*Blo + Alo*Bhi).
//   x: [E, M, K], w: [E, N, K], out: [E, M, N]; E=16, M=256, K=2048, N=8192.
// R9: 512 threads / 16 warps (2x8, warp tile 64x32) to raise warps/SMSP
// from 2 to 4 — R8 showed tensor idle cycles are latency exposure, not
// traffic. CTA tile stays 128x256, K-chunks of 32 fp32, double-buffered
// SMEM with 80B-padded rows (16B-aligned, conflict-free ldmatrix).

static constexpr int E_DIM = 16;
static constexpr int M_DIM = 256;
static constexpr int K_DIM = 2048;
static constexpr int N_DIM = 8192;

static constexpr int BM = 128;
static constexpr int BN = 256;
static constexpr int KC = 32;                 // fp32 k per chunk
static constexpr int NCHUNK = K_DIM / KC;     // 64

static constexpr int ROW_B   = 80;            // 64 B payload + 16 B pad
static constexpr int A_TILE  = 128 * ROW_B;   // 10240 B (one limb)
static constexpr int B_TILE  = 256 * ROW_B;   // 20480 B (one limb)
static constexpr int OFF_AHI = 0;
static constexpr int OFF_ALO = A_TILE;
static constexpr int OFF_BHI = 2 * A_TILE;
static constexpr int OFF_BLO = 2 * A_TILE + B_TILE;
static constexpr int STAGE_B = 2 * A_TILE + 2 * B_TILE;  // 61440
static constexpr int SMEM_B  = 2 * STAGE_B;              // 122880

__device__ __forceinline__ uint32_t smem_u32(const void* p) {
    uint32_t a;
    asm("{ .reg .u64 t; cvta.to.shared.u64 t, %1; cvt.u32.u64 %0, t; }"
        : "=r"(a) : "l"(p));
    return a;
}

__device__ __forceinline__ void split2(float x, float y, uint32_t& hi, uint32_t& lo) {
    __nv_bfloat162 h = __floats2bfloat162_rn(x, y);
    hi = *reinterpret_cast<uint32_t*>(&h);
    float hx = __uint_as_float(hi << 16);
    float hy = __uint_as_float(hi & 0xffff0000u);
    __nv_bfloat162 l = __floats2bfloat162_rn(x - hx, y - hy);
    lo = *reinterpret_cast<uint32_t*>(&l);
}

__device__ __forceinline__ void ldsm4(uint32_t* r, uint32_t addr) {
    asm volatile("ldmatrix.sync.aligned.m8n8.x4.shared.b16 {%0,%1,%2,%3}, [%4];"
                 : "=r"(r[0]), "=r"(r[1]), "=r"(r[2]), "=r"(r[3]) : "r"(addr));
}

__device__ __forceinline__ void mma16816(float* c, const uint32_t* a,
                                         const uint32_t* b) {
    asm volatile(
        "mma.sync.aligned.m16n8k16.row.col.f32.bf16.bf16.f32 "
        "{%0,%1,%2,%3}, {%4,%5,%6,%7}, {%8,%9}, {%0,%1,%2,%3};"
        : "+f"(c[0]), "+f"(c[1]), "+f"(c[2]), "+f"(c[3])
        : "r"(a[0]), "r"(a[1]), "r"(a[2]), "r"(a[3]), "r"(b[0]), "r"(b[1]));
}

__global__ __launch_bounds__(512, 1)
void grouped_gemm_hmma(const float* __restrict__ X,
                       const float* __restrict__ W,
                       float* __restrict__ O) {
    extern __shared__ char sm[];
    const uint32_t sbase = smem_u32(sm);

    const int tid  = threadIdx.x;
    const int wid  = tid >> 5;
    const int lane = tid & 31;
    const int wm   = wid >> 3;   // 0..1 -> 64-row slab
    const int wn   = wid & 7;    // 0..7 -> 32-col slab

    const int e  = blockIdx.z;
    const int m0 = blockIdx.y * BM;
    const int n0 = blockIdx.x * BN;

    // ---- global load mapping ----
    // A: 128 rows x 32 floats = 1024 float4; 512 thr -> 2 float4 (8 floats) each
    const int arow = tid >> 2;              // 0..127
    const int aq   = tid & 3;               // 8-float quarter of the row
    const float* Ag = X + ((size_t)e * M_DIM + m0 + arow) * K_DIM + aq * 8;
    const uint32_t wbA = arow * ROW_B + aq * 16;
    // B: 256 rows x 32 floats = 2048 float4; 512 thr -> 4 float4 (16 floats) each
    const int brow = tid >> 1;              // 0..255
    const int bhf  = tid & 1;               // 16-float half of the row
    const float* Bg = W + ((size_t)e * N_DIM + n0 + brow) * K_DIM + bhf * 16;
    const uint32_t wbB = brow * ROW_B + bhf * 32;

    // ---- ldmatrix offsets within a limb tile ----
    const uint32_t aoff = (uint32_t)((wm * 64 + (lane & 15)) * ROW_B + ((lane >> 4) << 4));
    const uint32_t boff = (uint32_t)((wn * 32 + ((lane >> 4) << 3) + (lane & 7)) * ROW_B
                                     + (((lane >> 3) & 1) << 4));

    float acc[4][4][4];
#pragma unroll
    for (int i = 0; i < 4; i++)
#pragma unroll
        for (int j = 0; j < 4; j++)
#pragma unroll
            for (int v = 0; v < 4; v++) acc[i][j][v] = 0.0f;

    float4 favA[2], favB[4];

    // ---- prologue: chunk 0 -> stage 0 ----
    favA[0] = *reinterpret_cast<const float4*>(Ag);
    favA[1] = *reinterpret_cast<const float4*>(Ag + 4);
#pragma unroll
    for (int j = 0; j < 4; j++)
        favB[j] = *reinterpret_cast<const float4*>(Bg + j * 4);
    {
        uint32_t h[4], l[4];
        split2(favA[0].x, favA[0].y, h[0], l[0]);
        split2(favA[0].z, favA[0].w, h[1], l[1]);
        split2(favA[1].x, favA[1].y, h[2], l[2]);
        split2(favA[1].z, favA[1].w, h[3], l[3]);
        *reinterpret_cast<uint4*>(sm + OFF_AHI + wbA) = make_uint4(h[0], h[1], h[2], h[3]);
        *reinterpret_cast<uint4*>(sm + OFF_ALO + wbA) = make_uint4(l[0], l[1], l[2], l[3]);
#pragma unroll
        for (int p = 0; p < 2; p++) {
            split2(favB[2 * p].x, favB[2 * p].y, h[0], l[0]);
            split2(favB[2 * p].z, favB[2 * p].w, h[1], l[1]);
            split2(favB[2 * p + 1].x, favB[2 * p + 1].y, h[2], l[2]);
            split2(favB[2 * p + 1].z, favB[2 * p + 1].w, h[3], l[3]);
            *reinterpret_cast<uint4*>(sm + OFF_BHI + wbB + p * 16) = make_uint4(h[0], h[1], h[2], h[3]);
            *reinterpret_cast<uint4*>(sm + OFF_BLO + wbB + p * 16) = make_uint4(l[0], l[1], l[2], l[3]);
        }
    }
    __syncthreads();

#pragma unroll 1
    for (int c = 0; c < NCHUNK; c++) {
        const bool more = (c + 1 < NCHUNK);
        if (more) {
            const int kof = (c + 1) * KC;
            favA[0] = *reinterpret_cast<const float4*>(Ag + kof);
            favA[1] = *reinterpret_cast<const float4*>(Ag + kof + 4);
#pragma unroll
            for (int j = 0; j < 4; j++)
                favB[j] = *reinterpret_cast<const float4*>(Bg + kof + j * 4);
        }

        const uint32_t st = sbase + (uint32_t)((c & 1) * STAGE_B);
        const uint32_t Ahi = st + OFF_AHI, Alo = st + OFF_ALO;
        const uint32_t Bhi = st + OFF_BHI, Blo = st + OFF_BLO;

#pragma unroll
        for (int ks = 0; ks < 2; ks++) {
            const uint32_t ksb = ks * 32;
            uint32_t bh[8], bl[8];
#pragma unroll
            for (int np = 0; np < 2; np++) {
                ldsm4(bh + 4 * np, Bhi + boff + np * (16 * ROW_B) + ksb);
                ldsm4(bl + 4 * np, Blo + boff + np * (16 * ROW_B) + ksb);
            }
#pragma unroll
            for (int mt = 0; mt < 4; mt++) {
                uint32_t ah[4], al[4];
                ldsm4(ah, Ahi + aoff + mt * (16 * ROW_B) + ksb);
                ldsm4(al, Alo + aoff + mt * (16 * ROW_B) + ksb);
#pragma unroll
                for (int nt = 0; nt < 4; nt++)
                    mma16816(acc[mt][nt], ah, bh + 2 * nt);
#pragma unroll
                for (int nt = 0; nt < 4; nt++)
                    mma16816(acc[mt][nt], ah, bl + 2 * nt);
#pragma unroll
                for (int nt = 0; nt < 4; nt++)
                    mma16816(acc[mt][nt], al, bh + 2 * nt);
            }

            // drain prefetch into the other stage between the two ks halves
            if (ks == 0 && more) {
                char* dst = sm + ((c + 1) & 1) * STAGE_B;
                uint32_t h[4], l[4];
                split2(favA[0].x, favA[0].y, h[0], l[0]);
                split2(favA[0].z, favA[0].w, h[1], l[1]);
                split2(favA[1].x, favA[1].y, h[2], l[2]);
                split2(favA[1].z, favA[1].w, h[3], l[3]);
                *reinterpret_cast<uint4*>(dst + OFF_AHI + wbA) = make_uint4(h[0], h[1], h[2], h[3]);
                *reinterpret_cast<uint4*>(dst + OFF_ALO + wbA) = make_uint4(l[0], l[1], l[2], l[3]);
#pragma unroll
                for (int p = 0; p < 2; p++) {
                    split2(favB[2 * p].x, favB[2 * p].y, h[0], l[0]);
                    split2(favB[2 * p].z, favB[2 * p].w, h[1], l[1]);
                    split2(favB[2 * p + 1].x, favB[2 * p + 1].y, h[2], l[2]);
                    split2(favB[2 * p + 1].z, favB[2 * p + 1].w, h[3], l[3]);
                    *reinterpret_cast<uint4*>(dst + OFF_BHI + wbB + p * 16) = make_uint4(h[0], h[1], h[2], h[3]);
                    *reinterpret_cast<uint4*>(dst + OFF_BLO + wbB + p * 16) = make_uint4(l[0], l[1], l[2], l[3]);
                }
            }
        }
        __syncthreads();
    }

    // ---- epilogue ----
    float* C = O + (size_t)e * M_DIM * N_DIM;
    const int mrow = m0 + wm * 64 + (lane >> 2);
    const int ncol = n0 + wn * 32 + (lane & 3) * 2;
#pragma unroll
    for (int mt = 0; mt < 4; mt++) {
#pragma unroll
        for (int nt = 0; nt < 4; nt++) {
            float* p0 = C + (size_t)(mrow + mt * 16) * N_DIM + (ncol + nt * 8);
            float* p1 = p0 + 8 * N_DIM;
            *reinterpret_cast<float2*>(p0) = make_float2(acc[mt][nt][0], acc[mt][nt][1]);
            *reinterpret_cast<float2*>(p1) = make_float2(acc[mt][nt][2], acc[mt][nt][3]);
        }
    }
}

extern "C" void kernel_launch(void* const* d_in, const int* in_sizes, int n_in,
                              void* d_out, int out_size) {
    const float* X = (const float*)d_in[0];  // expert_inputs  [E, M, K]
    const float* W = (const float*)d_in[1];  // expert_weights [E, N, K]
    float* O = (float*)d_out;                // [E, M, N]

    cudaFuncSetAttribute(grouped_gemm_hmma,
                         cudaFuncAttributeMaxDynamicSharedMemorySize, SMEM_B);

    dim3 grid(N_DIM / BN, M_DIM / BM, E_DIM);  // (32, 2, 16) = 1024 CTAs
    grouped_gemm_hmma<<<grid, 512, SMEM_B>>>(X, W, O);
}